// round 1
// baseline (speedup 1.0000x reference)
#include <cuda_runtime.h>
#include <math.h>

// Problem dims
#define NB 16
#define NC 256
#define NH 32
#define NW 32
#define NK 81
#define NHW 1024
#define NCHW (NC*NHW)
#define OUT_FLT (NB*NCHW)   // 4194304

// ---------------- device scratch (allocation-free) ----------------
__device__ float g_wlab[NK];
__device__ float g_wm[NK];      // target_mask (post-sigmoid)
__device__ float g_wsw[NK];     // spatial weight
__device__ float g_step;
__device__ float g_regw;
__device__ float g_flt[NB*NCHW];      // working filter
__device__ float g_fg[NB*NCHW];       // filter gradient
__device__ float g_mapped[NB*NK*NHW]; // mapped residuals
__device__ float g_maskw[NB*NK*NHW];  // sw * score_mask
__device__ float g_anum[NB*NHW];
__device__ float g_aden[NB*NHW];
__device__ float g_psrc[128];
__device__ float g_pfsq[128];
__device__ float g_losses[6];   // [iter*2+0]=src, [iter*2+1]=reg

// ---------------- init: distance-map weights + scalars ----------------
__global__ void k_init(const float* __restrict__ label_w,
                       const float* __restrict__ mask_w,
                       const float* __restrict__ spatial_w,
                       const float* __restrict__ logstep,
                       const float* __restrict__ freg) {
    int t = threadIdx.x;
    if (t < NK) {
        int k0 = t / 9, k1 = t % 9;
        float dist = sqrtf((float)((k0-4)*(k0-4) + (k1-4)*(k1-4)));
        float lab = 0.f, mk = 0.f, sw = 0.f;
        #pragma unroll
        for (int d = 0; d < 10; d++) {
            float diff = dist * 2.0f - (float)d;
            float bv;
            if (d < 9) bv = fmaxf(0.f, 1.f - fabsf(diff));
            else       bv = fminf(fmaxf(1.f + diff, 0.f), 1.f);
            lab += bv * label_w[d];
            mk  += bv * mask_w[d];
            sw  += bv * spatial_w[d];
        }
        g_wlab[t] = lab;
        g_wm[t]   = 1.f / (1.f + expf(-mk));
        g_wsw[t]  = sw;
    }
    if (t == 96) g_step = expf(logstep[0]);
    if (t == 97) {
        float fr = freg[0];
        g_regw = fmaxf(fr * fr, 1e-10f) / ((float)NC * (float)NC);
    }
}

// ---------------- copy input filter -> working buffer ----------------
__global__ void k_copy_in(const float* __restrict__ src) {
    int i = blockIdx.x * blockDim.x + threadIdx.x; // 1048576 float4
    ((float4*)g_flt)[i] = ((const float4*)src)[i];
}

// ---------------- K1: local corr + residual math + loss partials ----------------
// block = (batch, y-group of 4 rows): 128 blocks, 288 threads (yloc,dy,xg)
__global__ __launch_bounds__(288) void k_corr_res(const float* __restrict__ feat) {
    __shared__ __align__(16) float s_flt[16*4*32];    // [c][yloc][x]
    __shared__ __align__(16) float s_feat[16*12*40];  // [c][ry][j], padded halo
    __shared__ float s_red[64];

    int bi = blockIdx.x >> 3;
    int y0 = (blockIdx.x & 7) * 4;
    int tid = threadIdx.x;
    int yloc = tid / 72;
    int dy   = (tid % 72) / 8;
    int xg   = tid & 7;
    int x0   = xg * 4;

    const float* fltp  = g_flt + bi * NCHW;
    const float* featp = feat  + bi * NCHW;

    float acc[4][9];
    #pragma unroll
    for (int j = 0; j < 4; j++)
        #pragma unroll
        for (int d = 0; d < 9; d++) acc[j][d] = 0.f;
    float fsq = 0.f;

    for (int c0 = 0; c0 < NC; c0 += 16) {
        __syncthreads();
        for (int t = tid; t < 2048; t += 288) {
            int c = t >> 7; int r = t & 127; int yl = r >> 5; int x = r & 31;
            float v = fltp[(c0 + c) * NHW + (y0 + yl) * NW + x];
            s_flt[t] = v;
            fsq += v * v;
        }
        for (int t = tid; t < 7680; t += 288) {
            int c = t / 480; int r = t % 480; int ry = r / 40; int j = r % 40;
            int yy = y0 + ry - 4; int xx = j - 4;
            float v = (yy >= 0 && yy < NH && xx >= 0 && xx < NW)
                      ? featp[(c0 + c) * NHW + yy * NW + xx] : 0.f;
            s_feat[t] = v;
        }
        __syncthreads();
        int ry = yloc + dy;
        #pragma unroll 4
        for (int c = 0; c < 16; c++) {
            float4 f = *(const float4*)&s_flt[c*128 + yloc*32 + x0];
            const float* wp = &s_feat[c*480 + ry*40 + x0];
            float4 wa = *(const float4*)(wp);
            float4 wb = *(const float4*)(wp + 4);
            float4 wc = *(const float4*)(wp + 8);
            float w[12] = {wa.x,wa.y,wa.z,wa.w, wb.x,wb.y,wb.z,wb.w, wc.x,wc.y,wc.z,wc.w};
            #pragma unroll
            for (int dx = 0; dx < 9; dx++) {
                acc[0][dx] += f.x * w[dx];
                acc[1][dx] += f.y * w[dx+1];
                acc[2][dx] += f.z * w[dx+2];
                acc[3][dx] += f.w * w[dx+3];
            }
        }
    }

    // pointwise residual math
    float srcp = 0.f;
    int yy = y0 + yloc;
    #pragma unroll
    for (int dx = 0; dx < 9; dx++) {
        int k = dy * 9 + dx;
        float m  = g_wm[k];
        float lm = g_wlab[k];
        float sw = g_wsw[k];
        float a0 = 0.5f * (1.f - m);
        float a1 = 0.5f * (1.f + m);
        #pragma unroll
        for (int j = 0; j < 4; j++) {
            float s = acc[j][dx];
            float sact  = a0 * fabsf(s) + a1 * s;
            float sgn   = (s > 0.f) ? 1.f : ((s < 0.f) ? -1.f : 0.f);
            float smask = a0 * sgn + a1;
            float lres  = sw * (sact - lm);
            srcp += lres * lres;
            int gi = ((bi * NK + k) * NH + yy) * NW + x0 + j;
            g_mapped[gi] = smask * sw * lres;
            g_maskw[gi]  = sw * smask;
        }
    }

    // deterministic block reduction of srcp and fsq
    #pragma unroll
    for (int o = 16; o; o >>= 1) {
        srcp += __shfl_down_sync(0xffffffffu, srcp, o);
        fsq  += __shfl_down_sync(0xffffffffu, fsq,  o);
    }
    int wid = tid >> 5, lane = tid & 31;
    if (lane == 0) { s_red[wid] = srcp; s_red[32 + wid] = fsq; }
    __syncthreads();
    if (tid == 0) {
        float a = 0.f, b = 0.f;
        #pragma unroll
        for (int i = 0; i < 9; i++) { a += s_red[i]; b += s_red[32 + i]; }
        g_psrc[blockIdx.x] = a;
        g_pfsq[blockIdx.x] = b;
    }
}

// ---------------- loss partial reduction (fixed order) ----------------
__global__ void k_reduce(int iter) {
    __shared__ float s[8];
    int t = threadIdx.x; // 128
    float a = g_psrc[t];
    float b = g_pfsq[t];
    #pragma unroll
    for (int o = 16; o; o >>= 1) {
        a += __shfl_down_sync(0xffffffffu, a, o);
        b += __shfl_down_sync(0xffffffffu, b, o);
    }
    int wid = t >> 5, lane = t & 31;
    if (lane == 0) { s[wid] = a; s[4 + wid] = b; }
    __syncthreads();
    if (t == 0) {
        float sa = s[0] + s[1] + s[2] + s[3];
        float sb = s[4] + s[5] + s[6] + s[7];
        g_losses[iter * 2 + 0] = 0.5f * sa / (float)NB;
        g_losses[iter * 2 + 1] = 0.5f * g_regw * sb / (float)NB;
    }
}

// ---------------- K2: corr transpose + reg term + alpha_num ----------------
// block = (batch, y-group of 2 rows): 256 blocks, 128 threads (cp, yl, xg)
__global__ __launch_bounds__(128) void k_transpose(const float* __restrict__ feat) {
    __shared__ __align__(16) float s_res[2*81*32];    // 20.7 KB
    __shared__ __align__(16) float s_feat[16*10*40];  // 25.6 KB
    __shared__ float s_red[8*2*32];                   // 2 KB

    int bi = blockIdx.x >> 4;
    int y0 = (blockIdx.x & 15) * 2;
    int tid = threadIdx.x;
    int cp = tid >> 4;          // 0..7
    int yl = (tid >> 3) & 1;    // 0..1
    int xg = tid & 7;
    int x0 = xg * 4;

    const float* featp = feat  + bi * NCHW;
    const float* fltp  = g_flt + bi * NCHW;
    float regw = g_regw;

    for (int t = tid; t < 5184; t += 128) {
        int yy = t / 2592; int r = t % 2592; int k = r >> 5; int x = r & 31;
        s_res[t] = g_mapped[((bi * NK + k) * NH + y0 + yy) * NW + x];
    }

    float anum[4] = {0.f, 0.f, 0.f, 0.f};

    for (int c0 = 0; c0 < NC; c0 += 16) {
        __syncthreads();
        for (int t = tid; t < 6400; t += 128) {
            int c = t / 400; int r = t % 400; int ry = r / 40; int j = r % 40;
            int yy = y0 + ry - 4; int xx = j - 4;
            s_feat[t] = (yy >= 0 && yy < NH && xx >= 0 && xx < NW)
                        ? featp[(c0 + c) * NHW + yy * NW + xx] : 0.f;
        }
        __syncthreads();

        int c1 = cp * 2;
        float acc[2][4] = {{0.f,0.f,0.f,0.f},{0.f,0.f,0.f,0.f}};
        #pragma unroll
        for (int dy = 0; dy < 9; dy++) {
            float4 rr[9];
            #pragma unroll
            for (int dx = 0; dx < 9; dx++)
                rr[dx] = *(const float4*)&s_res[(yl * 81 + dy * 9 + dx) * 32 + x0];
            int ry = yl + dy;
            #pragma unroll
            for (int cc = 0; cc < 2; cc++) {
                const float* wp = &s_feat[(c1 + cc) * 400 + ry * 40 + x0];
                float4 wa = *(const float4*)(wp);
                float4 wb = *(const float4*)(wp + 4);
                float4 wc = *(const float4*)(wp + 8);
                float w[12] = {wa.x,wa.y,wa.z,wa.w, wb.x,wb.y,wb.z,wb.w, wc.x,wc.y,wc.z,wc.w};
                #pragma unroll
                for (int dx = 0; dx < 9; dx++) {
                    acc[cc][0] += rr[dx].x * w[dx];
                    acc[cc][1] += rr[dx].y * w[dx+1];
                    acc[cc][2] += rr[dx].z * w[dx+2];
                    acc[cc][3] += rr[dx].w * w[dx+3];
                }
            }
        }
        #pragma unroll
        for (int cc = 0; cc < 2; cc++) {
            int c = c0 + c1 + cc;
            int gi = (c * NH + y0 + yl) * NW + x0;
            float4 fv = *(const float4*)&fltp[gi];
            float4 o;
            o.x = acc[cc][0] + regw * fv.x;
            o.y = acc[cc][1] + regw * fv.y;
            o.z = acc[cc][2] + regw * fv.z;
            o.w = acc[cc][3] + regw * fv.w;
            *(float4*)&g_fg[bi * NCHW + gi] = o;
            anum[0] += o.x * o.x;
            anum[1] += o.y * o.y;
            anum[2] += o.z * o.z;
            anum[3] += o.w * o.w;
        }
    }

    __syncthreads();
    #pragma unroll
    for (int j = 0; j < 4; j++)
        s_red[(cp * 2 + yl) * 32 + x0 + j] = anum[j];
    __syncthreads();
    if (tid < 64) {
        int yy = tid >> 5, x = tid & 31;
        float a = 0.f;
        #pragma unroll
        for (int p = 0; p < 8; p++) a += s_red[(p * 2 + yy) * 32 + x];
        g_anum[bi * NHW + (y0 + yy) * NW + x] = a;
    }
}

// ---------------- K3: corr(filter_grad) -> sum_k scores_grad^2 ----------------
__global__ __launch_bounds__(288) void k_corr_grad(const float* __restrict__ feat) {
    __shared__ __align__(16) float s_flt[16*4*32];
    __shared__ __align__(16) float s_feat[16*12*40];
    __shared__ float s_part[9*4*32];

    int bi = blockIdx.x >> 3;
    int y0 = (blockIdx.x & 7) * 4;
    int tid = threadIdx.x;
    int yloc = tid / 72;
    int dy   = (tid % 72) / 8;
    int xg   = tid & 7;
    int x0   = xg * 4;

    const float* fgp   = g_fg + bi * NCHW;
    const float* featp = feat + bi * NCHW;

    float acc[4][9];
    #pragma unroll
    for (int j = 0; j < 4; j++)
        #pragma unroll
        for (int d = 0; d < 9; d++) acc[j][d] = 0.f;

    for (int c0 = 0; c0 < NC; c0 += 16) {
        __syncthreads();
        for (int t = tid; t < 2048; t += 288) {
            int c = t >> 7; int r = t & 127; int yl = r >> 5; int x = r & 31;
            s_flt[t] = fgp[(c0 + c) * NHW + (y0 + yl) * NW + x];
        }
        for (int t = tid; t < 7680; t += 288) {
            int c = t / 480; int r = t % 480; int ry = r / 40; int j = r % 40;
            int yy = y0 + ry - 4; int xx = j - 4;
            s_feat[t] = (yy >= 0 && yy < NH && xx >= 0 && xx < NW)
                        ? featp[(c0 + c) * NHW + yy * NW + xx] : 0.f;
        }
        __syncthreads();
        int ry = yloc + dy;
        #pragma unroll 4
        for (int c = 0; c < 16; c++) {
            float4 f = *(const float4*)&s_flt[c*128 + yloc*32 + x0];
            const float* wp = &s_feat[c*480 + ry*40 + x0];
            float4 wa = *(const float4*)(wp);
            float4 wb = *(const float4*)(wp + 4);
            float4 wc = *(const float4*)(wp + 8);
            float w[12] = {wa.x,wa.y,wa.z,wa.w, wb.x,wb.y,wb.z,wb.w, wc.x,wc.y,wc.z,wc.w};
            #pragma unroll
            for (int dx = 0; dx < 9; dx++) {
                acc[0][dx] += f.x * w[dx];
                acc[1][dx] += f.y * w[dx+1];
                acc[2][dx] += f.z * w[dx+2];
                acc[3][dx] += f.w * w[dx+3];
            }
        }
    }

    float denl[4] = {0.f, 0.f, 0.f, 0.f};
    int yy = y0 + yloc;
    #pragma unroll
    for (int dx = 0; dx < 9; dx++) {
        int k = dy * 9 + dx;
        #pragma unroll
        for (int j = 0; j < 4; j++) {
            int gi = ((bi * NK + k) * NH + yy) * NW + x0 + j;
            float sg = g_maskw[gi] * acc[j][dx];
            denl[j] += sg * sg;
        }
    }
    #pragma unroll
    for (int j = 0; j < 4; j++)
        s_part[(dy * 4 + yloc) * 32 + x0 + j] = denl[j];
    __syncthreads();
    if (tid < 128) {
        int yl = tid >> 5, x = tid & 31;
        float d = 0.f;
        #pragma unroll
        for (int q = 0; q < 9; q++) d += s_part[(q * 4 + yl) * 32 + x];
        g_aden[bi * NHW + (y0 + yl) * NW + x] = d;
    }
}

// ---------------- K4: per-pixel alpha + filter update ----------------
__global__ void k_update() {
    int i = blockIdx.x * blockDim.x + threadIdx.x; // 4194304 total
    int b = i / NCHW;
    int p = i & (NHW - 1);
    float num = g_anum[b * NHW + p];
    float den = g_aden[b * NHW + p];
    float ad = fmaxf(den + g_regw * num, 1e-8f);
    float alpha = num / ad;
    g_flt[i] -= g_step * alpha * g_fg[i];
}

// ---------------- final: write output ----------------
__global__ void k_final(float* __restrict__ out) {
    int i = blockIdx.x * blockDim.x + threadIdx.x; // 1048576 float4
    ((float4*)out)[i] = ((const float4*)g_flt)[i];
    if (blockIdx.x == 0 && threadIdx.x < 9) {
        int t = threadIdx.x;
        float v;
        if (t < 3)       v = g_losses[t * 2] + g_losses[t * 2 + 1]; // tr
        else if (t < 6)  v = g_losses[(t - 3) * 2];                  // tr_src
        else             v = g_losses[(t - 6) * 2 + 1];              // tr_reg
        out[OUT_FLT + t] = v;
    }
}

extern "C" void kernel_launch(void* const* d_in, const int* in_sizes, int n_in,
                              void* d_out, int out_size) {
    const float* flt  = (const float*)d_in[0];
    const float* feat = (const float*)d_in[1];
    const float* lw   = (const float*)d_in[2];
    const float* mw   = (const float*)d_in[3];
    const float* sw   = (const float*)d_in[4];
    const float* ls   = (const float*)d_in[5];
    const float* fr   = (const float*)d_in[6];

    k_init<<<1, 128>>>(lw, mw, sw, ls, fr);
    k_copy_in<<<2048, 512>>>(flt);
    for (int it = 0; it < 3; it++) {
        k_corr_res<<<128, 288>>>(feat);
        k_reduce<<<1, 128>>>(it);
        k_transpose<<<256, 128>>>(feat);
        k_corr_grad<<<128, 288>>>(feat);
        k_update<<<4096, 1024>>>();
    }
    k_final<<<2048, 512>>>((float*)d_out);
}

// round 2
// speedup vs baseline: 2.2473x; 2.2473x over previous
#include <cuda_runtime.h>
#include <math.h>

#define NB 16
#define NC 256
#define NH 32
#define NW 32
#define NK 81
#define NHW 1024
#define NCHW (NC*NHW)
#define OUT_FLT (NB*NCHW)
#define FPAD 1600              // 40*40 padded plane
#define FPAD_C (NC*FPAD)

// ---------------- device scratch (allocation-free) ----------------
__device__ float g_wlab[NK];
__device__ float g_wm[NK];
__device__ float g_wsw[NK];
__device__ float g_step;
__device__ float g_regw;
__device__ float g_flt[NB*NCHW];
__device__ float g_fg[NB*NCHW];
__device__ float g_mapped[NB*NK*NHW];
__device__ float g_maskw[NB*NK*NHW];
__device__ float g_anum[NB*NHW];
__device__ float g_featpad[NB*FPAD_C];   // 26.2 MB
__device__ float g_psrc[128];
__device__ float g_pfsq[128];
__device__ float g_losses[6];

// ---------------- init ----------------
__global__ void k_init(const float* __restrict__ label_w,
                       const float* __restrict__ mask_w,
                       const float* __restrict__ spatial_w,
                       const float* __restrict__ logstep,
                       const float* __restrict__ freg) {
    int t = threadIdx.x;
    if (t < NK) {
        int k0 = t / 9, k1 = t % 9;
        float dist = sqrtf((float)((k0-4)*(k0-4) + (k1-4)*(k1-4)));
        float lab = 0.f, mk = 0.f, sw = 0.f;
        #pragma unroll
        for (int d = 0; d < 10; d++) {
            float diff = dist * 2.0f - (float)d;
            float bv;
            if (d < 9) bv = fmaxf(0.f, 1.f - fabsf(diff));
            else       bv = fminf(fmaxf(1.f + diff, 0.f), 1.f);
            lab += bv * label_w[d];
            mk  += bv * mask_w[d];
            sw  += bv * spatial_w[d];
        }
        g_wlab[t] = lab;
        g_wm[t]   = 1.f / (1.f + expf(-mk));
        g_wsw[t]  = sw;
    }
    if (t == 96) g_step = expf(logstep[0]);
    if (t == 97) {
        float fr = freg[0];
        g_regw = fmaxf(fr * fr, 1e-10f) / ((float)NC * (float)NC);
    }
}

// ---------------- pre-pad feat into [B][C][40][40] ----------------
__global__ void k_prepad(const float* __restrict__ feat) {
    int bc = blockIdx.x;                    // 4096 planes
    const float* src = feat + bc * NHW;
    float* dst = g_featpad + bc * FPAD;
    for (int t = threadIdx.x; t < FPAD; t += 128) {
        int py = t / 40, px = t - py * 40;
        float v = 0.f;
        if (py >= 4 && py < 36 && px >= 4 && px < 36)
            v = src[(py - 4) * NW + (px - 4)];
        dst[t] = v;
    }
}

// ---------------- K1: corr + residual math + loss partials ----------------
// 128 blocks x 576 threads; two channel-halves per block; 8-ch chunks
__global__ __launch_bounds__(576) void k_corr_res(const float* __restrict__ flt_in, int use_in) {
    __shared__ float s[11648];
    int tid = threadIdx.x;
    int h = tid / 288;
    int r = tid - h * 288;
    int yloc = r / 72;
    int q = r - yloc * 72;
    int dy = q >> 3;
    int xg = q & 7;
    int x0 = xg * 4;
    int bi = blockIdx.x >> 3;
    int y0 = (blockIdx.x & 7) * 4;

    const float* fbase = use_in ? flt_in : g_flt;
    const float* fltp = fbase + bi * NCHW;
    const float* fpb  = g_featpad + bi * FPAD_C;
    float* sflt  = s + h * 1024;
    float* sfeat = s + 2048 + h * 3840;

    float acc[4][9];
    #pragma unroll
    for (int j = 0; j < 4; j++)
        #pragma unroll
        for (int d = 0; d < 9; d++) acc[j][d] = 0.f;
    float fsq = 0.f;

    for (int ci = 0; ci < 16; ci++) {
        int cbase = ci * 16 + h * 8;
        __syncthreads();
        if (r < 256) {
            int c = r >> 5, e = r & 31;
            float4 v = ((const float4*)(fltp + (cbase + c) * NHW + y0 * NW))[e];
            ((float4*)sflt)[r] = v;
            fsq += v.x*v.x + v.y*v.y + v.z*v.z + v.w*v.w;
        }
        for (int t = r; t < 960; t += 288) {
            int c = t / 120; int rem = t - c * 120; int ry = rem / 10; int e = rem - ry * 10;
            ((float4*)sfeat)[t] = ((const float4*)(fpb + (cbase + c) * FPAD + (y0 + ry) * 40))[e];
        }
        __syncthreads();
        int ry = yloc + dy;
        #pragma unroll
        for (int c = 0; c < 8; c++) {
            float4 f = *(const float4*)&sflt[c * 128 + yloc * 32 + x0];
            const float* wp = &sfeat[c * 480 + ry * 40 + x0];
            float4 wa = *(const float4*)wp;
            float4 wb = *(const float4*)(wp + 4);
            float4 wc = *(const float4*)(wp + 8);
            float w[12] = {wa.x,wa.y,wa.z,wa.w, wb.x,wb.y,wb.z,wb.w, wc.x,wc.y,wc.z,wc.w};
            #pragma unroll
            for (int dx = 0; dx < 9; dx++) {
                acc[0][dx] += f.x * w[dx];
                acc[1][dx] += f.y * w[dx+1];
                acc[2][dx] += f.z * w[dx+2];
                acc[3][dx] += f.w * w[dx+3];
            }
        }
    }

    __syncthreads();
    if (h == 1) {
        float* ap = s + r * 36;
        #pragma unroll
        for (int j = 0; j < 4; j++)
            #pragma unroll
            for (int dx = 0; dx < 9; dx++) ap[j * 9 + dx] = acc[j][dx];
    }
    __syncthreads();

    float srcp = 0.f;
    if (h == 0) {
        const float* ap = s + r * 36;
        int yy = y0 + yloc;
        #pragma unroll
        for (int dx = 0; dx < 9; dx++) {
            int k = dy * 9 + dx;
            float m  = g_wm[k];
            float lm = g_wlab[k];
            float sw = g_wsw[k];
            float a0 = 0.5f * (1.f - m);
            float a1 = 0.5f * (1.f + m);
            #pragma unroll
            for (int j = 0; j < 4; j++) {
                float sv = acc[j][dx] + ap[j * 9 + dx];
                float sact  = a0 * fabsf(sv) + a1 * sv;
                float sgn   = (sv > 0.f) ? 1.f : ((sv < 0.f) ? -1.f : 0.f);
                float smask = a0 * sgn + a1;
                float lres  = sw * (sact - lm);
                srcp += lres * lres;
                int gi = ((bi * NK + k) * NH + yy) * NW + x0 + j;
                g_mapped[gi] = smask * sw * lres;
                g_maskw[gi]  = sw * smask;
            }
        }
    }

    #pragma unroll
    for (int o = 16; o; o >>= 1) {
        srcp += __shfl_down_sync(0xffffffffu, srcp, o);
        fsq  += __shfl_down_sync(0xffffffffu, fsq,  o);
    }
    __syncthreads();
    int wid = tid >> 5, lane = tid & 31;
    if (lane == 0) { s[wid] = srcp; s[32 + wid] = fsq; }
    __syncthreads();
    if (tid == 0) {
        float a = 0.f, b = 0.f;
        #pragma unroll
        for (int i = 0; i < 9; i++) a += s[i];
        #pragma unroll
        for (int i = 0; i < 18; i++) b += s[32 + i];
        g_psrc[blockIdx.x] = a;
        g_pfsq[blockIdx.x] = b;
    }
}

// ---------------- K2: transpose + reg + anum (+ folded loss reduce) ----------------
// 256 blocks x 256 threads
__global__ __launch_bounds__(256) void k_transpose(const float* __restrict__ flt_in,
                                                   int use_in, int iter) {
    __shared__ float s[11584];   // s_res [0..5183] = [81][2][32]; s_feat at 5184 (6400)
    int tid = threadIdx.x;
    int bi = blockIdx.x >> 4;
    int y0 = (blockIdx.x & 15) * 2;
    int cslot = tid >> 4;
    int yl = (tid >> 3) & 1;
    int xg = tid & 7;
    int x0 = xg * 4;

    // folded loss reduction (warp 0 of block 0)
    if (blockIdx.x == 0 && tid < 32) {
        float a = g_psrc[tid] + g_psrc[tid+32] + g_psrc[tid+64] + g_psrc[tid+96];
        float b = g_pfsq[tid] + g_pfsq[tid+32] + g_pfsq[tid+64] + g_pfsq[tid+96];
        #pragma unroll
        for (int o = 16; o; o >>= 1) {
            a += __shfl_down_sync(0xffffffffu, a, o);
            b += __shfl_down_sync(0xffffffffu, b, o);
        }
        if (tid == 0) {
            g_losses[iter * 2 + 0] = 0.5f * a / (float)NB;
            g_losses[iter * 2 + 1] = 0.5f * g_regw * b / (float)NB;
        }
    }

    const float* mp = g_mapped + bi * NK * NHW + y0 * NW;
    for (int t = tid; t < 1296; t += 256) {
        int k = t >> 4; int e = t & 15;
        ((float4*)s)[t] = ((const float4*)(mp + k * NHW))[e];
    }

    const float* fbase = use_in ? flt_in : g_flt;
    const float* fltp = fbase + bi * NCHW;
    const float* fpb  = g_featpad + bi * FPAD_C;
    float* fgb = g_fg + bi * NCHW;
    float regw = g_regw;
    float* sfeat = s + 5184;
    float an0 = 0.f, an1 = 0.f, an2 = 0.f, an3 = 0.f;

    for (int ci = 0; ci < 16; ci++) {
        __syncthreads();
        for (int t = tid; t < 1600; t += 256) {
            int c = t / 100; int rem = t - c * 100; int ry = rem / 10; int e = rem - ry * 10;
            ((float4*)sfeat)[t] = ((const float4*)(fpb + (ci * 16 + c) * FPAD + (y0 + ry) * 40))[e];
        }
        __syncthreads();

        float a0 = 0.f, a1 = 0.f, a2 = 0.f, a3 = 0.f;
        const float* resb  = s + yl * 32 + x0;
        const float* wbase = sfeat + cslot * 400 + yl * 40 + x0;
        #pragma unroll
        for (int dyy = 0; dyy < 9; dyy++) {
            const float* wp = wbase + dyy * 40;
            float4 wa = *(const float4*)wp;
            float4 wb = *(const float4*)(wp + 4);
            float4 wc = *(const float4*)(wp + 8);
            float w[12] = {wa.x,wa.y,wa.z,wa.w, wb.x,wb.y,wb.z,wb.w, wc.x,wc.y,wc.z,wc.w};
            #pragma unroll
            for (int dx = 0; dx < 9; dx++) {
                float4 rr = *(const float4*)(resb + (dyy * 9 + dx) * 64);
                a0 += rr.x * w[dx];
                a1 += rr.y * w[dx+1];
                a2 += rr.z * w[dx+2];
                a3 += rr.w * w[dx+3];
            }
        }
        int cg = ci * 16 + cslot;
        int gi = cg * NHW + (y0 + yl) * NW + x0;
        float4 fv = *(const float4*)(fltp + gi);
        float4 o;
        o.x = a0 + regw * fv.x;
        o.y = a1 + regw * fv.y;
        o.z = a2 + regw * fv.z;
        o.w = a3 + regw * fv.w;
        *(float4*)(fgb + gi) = o;
        an0 += o.x * o.x; an1 += o.y * o.y; an2 += o.z * o.z; an3 += o.w * o.w;
    }

    __syncthreads();
    s[cslot * 64 + yl * 32 + x0 + 0] = an0;
    s[cslot * 64 + yl * 32 + x0 + 1] = an1;
    s[cslot * 64 + yl * 32 + x0 + 2] = an2;
    s[cslot * 64 + yl * 32 + x0 + 3] = an3;
    __syncthreads();
    if (tid < 64) {
        int yy = tid >> 5, x = tid & 31;
        float a = 0.f;
        #pragma unroll
        for (int cs = 0; cs < 16; cs++) a += s[cs * 64 + yy * 32 + x];
        g_anum[bi * NHW + (y0 + yy) * NW + x] = a;
    }
}

// ---------------- K3: corr(fg) -> aden -> alpha -> fused filter update ----------------
__global__ __launch_bounds__(576) void k_corr_grad(const float* __restrict__ flt_in, int use_in) {
    __shared__ float s[11648];
    int tid = threadIdx.x;
    int h = tid / 288;
    int r = tid - h * 288;
    int yloc = r / 72;
    int q = r - yloc * 72;
    int dy = q >> 3;
    int xg = q & 7;
    int x0 = xg * 4;
    int bi = blockIdx.x >> 3;
    int y0 = (blockIdx.x & 7) * 4;

    const float* fgp = g_fg + bi * NCHW;
    const float* fpb = g_featpad + bi * FPAD_C;
    float* sflt  = s + h * 1024;
    float* sfeat = s + 2048 + h * 3840;

    float acc[4][9];
    #pragma unroll
    for (int j = 0; j < 4; j++)
        #pragma unroll
        for (int d = 0; d < 9; d++) acc[j][d] = 0.f;

    for (int ci = 0; ci < 16; ci++) {
        int cbase = ci * 16 + h * 8;
        __syncthreads();
        if (r < 256) {
            int c = r >> 5, e = r & 31;
            ((float4*)sflt)[r] = ((const float4*)(fgp + (cbase + c) * NHW + y0 * NW))[e];
        }
        for (int t = r; t < 960; t += 288) {
            int c = t / 120; int rem = t - c * 120; int ry = rem / 10; int e = rem - ry * 10;
            ((float4*)sfeat)[t] = ((const float4*)(fpb + (cbase + c) * FPAD + (y0 + ry) * 40))[e];
        }
        __syncthreads();
        int ry = yloc + dy;
        #pragma unroll
        for (int c = 0; c < 8; c++) {
            float4 f = *(const float4*)&sflt[c * 128 + yloc * 32 + x0];
            const float* wp = &sfeat[c * 480 + ry * 40 + x0];
            float4 wa = *(const float4*)wp;
            float4 wb = *(const float4*)(wp + 4);
            float4 wc = *(const float4*)(wp + 8);
            float w[12] = {wa.x,wa.y,wa.z,wa.w, wb.x,wb.y,wb.z,wb.w, wc.x,wc.y,wc.z,wc.w};
            #pragma unroll
            for (int dx = 0; dx < 9; dx++) {
                acc[0][dx] += f.x * w[dx];
                acc[1][dx] += f.y * w[dx+1];
                acc[2][dx] += f.z * w[dx+2];
                acc[3][dx] += f.w * w[dx+3];
            }
        }
    }

    __syncthreads();
    if (h == 1) {
        float* ap = s + r * 36;
        #pragma unroll
        for (int j = 0; j < 4; j++)
            #pragma unroll
            for (int dx = 0; dx < 9; dx++) ap[j * 9 + dx] = acc[j][dx];
    }
    __syncthreads();

    if (h == 0) {
        const float* ap = s + r * 36;
        int yy = y0 + yloc;
        float denl[4] = {0.f, 0.f, 0.f, 0.f};
        #pragma unroll
        for (int dx = 0; dx < 9; dx++) {
            int k = dy * 9 + dx;
            #pragma unroll
            for (int j = 0; j < 4; j++) {
                int gi = ((bi * NK + k) * NH + yy) * NW + x0 + j;
                float sg = g_maskw[gi] * (acc[j][dx] + ap[j * 9 + dx]);
                denl[j] += sg * sg;
            }
        }
        #pragma unroll
        for (int j = 0; j < 4; j++)
            s[10368 + (dy * 4 + yloc) * 32 + x0 + j] = denl[j];
    }
    __syncthreads();

    if (tid < 128) {
        int yl = tid >> 5, x = tid & 31;
        float d = 0.f;
        #pragma unroll
        for (int qq = 0; qq < 9; qq++) d += s[10368 + (qq * 4 + yl) * 32 + x];
        float num = g_anum[bi * NHW + (y0 + yl) * NW + x];
        float ad = fmaxf(d + g_regw * num, 1e-8f);
        s[11520 + yl * 32 + x] = num / ad;
    }
    __syncthreads();

    // fused filter update for this block's (bi, 4 rows)
    const float* fbase = use_in ? flt_in : g_flt;
    float step = g_step;
    for (int t = tid; t < 8192; t += 576) {
        int c = t >> 5; int e = t & 31; int row = e >> 3; int xq = e & 7;
        int gi = bi * NCHW + c * NHW + (y0 + row) * NW + xq * 4;
        float4 fg4 = *(const float4*)(g_fg + gi);
        float4 fv  = *(const float4*)(fbase + gi);
        float al0 = s[11520 + row * 32 + xq * 4 + 0];
        float al1 = s[11520 + row * 32 + xq * 4 + 1];
        float al2 = s[11520 + row * 32 + xq * 4 + 2];
        float al3 = s[11520 + row * 32 + xq * 4 + 3];
        float4 o;
        o.x = fv.x - step * al0 * fg4.x;
        o.y = fv.y - step * al1 * fg4.y;
        o.z = fv.z - step * al2 * fg4.z;
        o.w = fv.w - step * al3 * fg4.w;
        *(float4*)(g_flt + gi) = o;
    }
}

// ---------------- final ----------------
__global__ void k_final(float* __restrict__ out) {
    int i = blockIdx.x * blockDim.x + threadIdx.x;
    ((float4*)out)[i] = ((const float4*)g_flt)[i];
    if (blockIdx.x == 0 && threadIdx.x < 9) {
        int t = threadIdx.x;
        float v;
        if (t < 3)       v = g_losses[t * 2] + g_losses[t * 2 + 1];
        else if (t < 6)  v = g_losses[(t - 3) * 2];
        else             v = g_losses[(t - 6) * 2 + 1];
        out[OUT_FLT + t] = v;
    }
}

extern "C" void kernel_launch(void* const* d_in, const int* in_sizes, int n_in,
                              void* d_out, int out_size) {
    const float* flt  = (const float*)d_in[0];
    const float* feat = (const float*)d_in[1];
    const float* lw   = (const float*)d_in[2];
    const float* mw   = (const float*)d_in[3];
    const float* sw   = (const float*)d_in[4];
    const float* ls   = (const float*)d_in[5];
    const float* fr   = (const float*)d_in[6];

    k_init<<<1, 128>>>(lw, mw, sw, ls, fr);
    k_prepad<<<4096, 128>>>(feat);
    for (int it = 0; it < 3; it++) {
        int first = (it == 0) ? 1 : 0;
        k_corr_res<<<128, 576>>>(flt, first);
        k_transpose<<<256, 256>>>(flt, first, it);
        k_corr_grad<<<128, 576>>>(flt, first);
    }
    k_final<<<2048, 512>>>((float*)d_out);
}

// round 3
// speedup vs baseline: 2.5034x; 1.1140x over previous
#include <cuda_runtime.h>
#include <math.h>

#define NB 16
#define NC 256
#define NH 32
#define NW 32
#define NK 81
#define NHW 1024
#define NCHW (NC*NHW)
#define OUT_FLT (NB*NCHW)
#define FPAD 1600              // 40*40 padded plane
#define FPAD_C (NC*FPAD)

// ---------------- device scratch ----------------
__device__ float g_wlab[NK], g_wm[NK], g_wsw[NK];
__device__ float g_step, g_regw;
__device__ float g_flt[NB*NCHW];
__device__ float g_fg[NB*NCHW];
__device__ float g_mapped[NB*NK*NHW];
__device__ float g_maskw[NB*NK*NHW];
__device__ float g_anum[2*NB*NHW];       // two channel-halves
__device__ float g_featpad[NB*FPAD_C];
__device__ float g_psrc[512], g_pfsq[512];
__device__ float g_losses[6];

// ---------------- init ----------------
__global__ void k_init(const float* __restrict__ label_w,
                       const float* __restrict__ mask_w,
                       const float* __restrict__ spatial_w,
                       const float* __restrict__ logstep,
                       const float* __restrict__ freg) {
    int t = threadIdx.x;
    if (t < NK) {
        int k0 = t / 9, k1 = t % 9;
        float dist = sqrtf((float)((k0-4)*(k0-4) + (k1-4)*(k1-4)));
        float lab = 0.f, mk = 0.f, sw = 0.f;
        #pragma unroll
        for (int d = 0; d < 10; d++) {
            float diff = dist * 2.0f - (float)d;
            float bv;
            if (d < 9) bv = fmaxf(0.f, 1.f - fabsf(diff));
            else       bv = fminf(fmaxf(1.f + diff, 0.f), 1.f);
            lab += bv * label_w[d];
            mk  += bv * mask_w[d];
            sw  += bv * spatial_w[d];
        }
        g_wlab[t] = lab;
        g_wm[t]   = 1.f / (1.f + expf(-mk));
        g_wsw[t]  = sw;
    }
    if (t == 96) g_step = expf(logstep[0]);
    if (t == 97) {
        float fr = freg[0];
        g_regw = fmaxf(fr * fr, 1e-10f) / ((float)NC * (float)NC);
    }
}

// ---------------- pre-pad feat (float4) ----------------
__global__ void k_prepad(const float* __restrict__ feat) {
    int bc = blockIdx.x;
    const float* src = feat + bc * NHW;
    float4* dst = (float4*)(g_featpad + bc * FPAD);
    for (int t = threadIdx.x; t < 400; t += 128) {
        int py = t / 10, e = t - py * 10;
        float4 v = make_float4(0.f, 0.f, 0.f, 0.f);
        if (py >= 4 && py < 36 && e >= 1 && e <= 8)
            v = *(const float4*)(src + (py - 4) * NW + e * 4 - 4);
        dst[t] = v;
    }
}

// ---------------- K1: corr + residual math ----------------
// 512 blocks (bi*32 + y), 288 threads = 4 quarters x (dy9 x xg8)
__global__ __launch_bounds__(288) void k_corr_res(const float* __restrict__ flt_in, int use_in) {
    __shared__ float s[8128];
    int tid = threadIdx.x;
    int h = tid / 72;
    int r = tid - h * 72;
    int dy = r >> 3;
    int x0 = (r & 7) * 4;
    int bi = blockIdx.x >> 5;
    int y0 = blockIdx.x & 31;

    const float* fltp = (use_in ? flt_in : g_flt) + bi * NCHW + y0 * NW;
    const float* fpb  = g_featpad + bi * FPAD_C + y0 * 40;
    float* sflt  = s + h * 128;
    float* sfeat = s + 512 + h * 1440;

    float acc[4][9];
    #pragma unroll
    for (int j = 0; j < 4; j++)
        #pragma unroll
        for (int d = 0; d < 9; d++) acc[j][d] = 0.f;
    float fsq = 0.f;

    for (int ci = 0; ci < 16; ci++) {
        int cb = (h << 6) + (ci << 2);
        __syncthreads();
        if (r < 32) {
            int c = r >> 3, e = r & 7;
            float4 v = *(const float4*)(fltp + (cb + c) * NHW + e * 4);
            *(float4*)(sflt + c * 32 + e * 4) = v;
            fsq += v.x*v.x + v.y*v.y + v.z*v.z + v.w*v.w;
        }
        #pragma unroll
        for (int i = 0; i < 5; i++) {
            int t = r + i * 72;
            int c = t / 90; int rem = t - c * 90;
            int ry = rem / 10; int e = rem - ry * 10;
            *(float4*)(sfeat + c * 360 + ry * 40 + e * 4) =
                *(const float4*)(fpb + (cb + c) * FPAD + ry * 40 + e * 4);
        }
        __syncthreads();
        #pragma unroll
        for (int c = 0; c < 4; c++) {
            float4 f = *(const float4*)(sflt + c * 32 + x0);
            const float* wp = sfeat + c * 360 + dy * 40 + x0;
            float4 wa = *(const float4*)wp;
            float4 wb = *(const float4*)(wp + 4);
            float4 wc = *(const float4*)(wp + 8);
            float w[12] = {wa.x,wa.y,wa.z,wa.w, wb.x,wb.y,wb.z,wb.w, wc.x,wc.y,wc.z,wc.w};
            #pragma unroll
            for (int dx = 0; dx < 9; dx++) {
                acc[0][dx] += f.x * w[dx];
                acc[1][dx] += f.y * w[dx+1];
                acc[2][dx] += f.z * w[dx+2];
                acc[3][dx] += f.w * w[dx+3];
            }
        }
    }

    __syncthreads();
    if (h > 0) {
        float* ap = s + (h - 1) * 2592 + r * 36;
        #pragma unroll
        for (int j = 0; j < 4; j++)
            #pragma unroll
            for (int dx = 0; dx < 9; dx++) ap[j * 9 + dx] = acc[j][dx];
    }
    __syncthreads();

    float srcp = 0.f;
    if (h == 0) {
        #pragma unroll
        for (int hh = 0; hh < 3; hh++) {
            const float* ap = s + hh * 2592 + r * 36;
            #pragma unroll
            for (int j = 0; j < 4; j++)
                #pragma unroll
                for (int dx = 0; dx < 9; dx++) acc[j][dx] += ap[j * 9 + dx];
        }
        #pragma unroll
        for (int dx = 0; dx < 9; dx++) {
            int k = dy * 9 + dx;
            float m  = g_wm[k];
            float lm = g_wlab[k];
            float sw = g_wsw[k];
            float a0 = 0.5f * (1.f - m);
            float a1 = 0.5f * (1.f + m);
            #pragma unroll
            for (int j = 0; j < 4; j++) {
                float sv = acc[j][dx];
                float sact  = a0 * fabsf(sv) + a1 * sv;
                float sgn   = (sv > 0.f) ? 1.f : ((sv < 0.f) ? -1.f : 0.f);
                float smask = a0 * sgn + a1;
                float lres  = sw * (sact - lm);
                srcp += lres * lres;
                int gi = ((bi * NK + k) * NH + y0) * NW + x0 + j;
                g_mapped[gi] = smask * sw * lres;
                g_maskw[gi]  = sw * smask;
            }
        }
    }

    #pragma unroll
    for (int o = 16; o; o >>= 1) {
        srcp += __shfl_down_sync(0xffffffffu, srcp, o);
        fsq  += __shfl_down_sync(0xffffffffu, fsq,  o);
    }
    int wid = tid >> 5, lane = tid & 31;
    if (lane == 0) { s[7776 + wid] = srcp; s[7808 + wid] = fsq; }
    __syncthreads();
    if (tid == 0) {
        float a = 0.f, b = 0.f;
        #pragma unroll
        for (int i = 0; i < 9; i++) { a += s[7776 + i]; b += s[7808 + i]; }
        g_psrc[blockIdx.x] = a;
        g_pfsq[blockIdx.x] = b;
    }
}

// ---------------- K2: transpose + reg + anum (channel-split) ----------------
// 512 blocks = bi(16) x ypair(16) x half(2); 128 threads = cslot8(2ch) x yl2 x xg8
__global__ __launch_bounds__(128) void k_transpose(const float* __restrict__ flt_in,
                                                   int use_in, int iter) {
    __shared__ float s[11584];   // s_res [0..5184), s_feat [5184..11584)
    int tid = threadIdx.x;
    int bx = blockIdx.x;
    int bi = bx >> 5;
    int r5 = bx & 31;
    int y0 = (r5 >> 1) << 1;
    int hf = r5 & 1;
    int cslot = tid >> 4;
    int yl = (tid >> 3) & 1;
    int x0 = (tid & 7) * 4;

    if (bx == 0 && tid < 32) {
        float a = 0.f, b = 0.f;
        #pragma unroll
        for (int i = 0; i < 16; i++) { a += g_psrc[tid + 32*i]; b += g_pfsq[tid + 32*i]; }
        #pragma unroll
        for (int o = 16; o; o >>= 1) {
            a += __shfl_down_sync(0xffffffffu, a, o);
            b += __shfl_down_sync(0xffffffffu, b, o);
        }
        if (tid == 0) {
            g_losses[iter * 2 + 0] = 0.5f * a / (float)NB;
            g_losses[iter * 2 + 1] = 0.5f * g_regw * b / (float)NB;
        }
    }

    const float* mp = g_mapped + bi * NK * NHW + y0 * NW;
    for (int t = tid; t < 1296; t += 128) {
        int k = t >> 4; int e = t & 15;
        ((float4*)s)[t] = ((const float4*)(mp + k * NHW))[e];
    }

    const float* fltp = (use_in ? flt_in : g_flt) + bi * NCHW;
    const float* fpb  = g_featpad + bi * FPAD_C;
    float* fgb = g_fg + bi * NCHW;
    float regw = g_regw;
    float* sfeat = s + 5184;
    float an[4] = {0.f, 0.f, 0.f, 0.f};

    for (int ci = 0; ci < 8; ci++) {
        int cb = (hf << 7) + (ci << 4);
        __syncthreads();
        for (int t = tid; t < 1600; t += 128) {
            int c = t / 100; int rem = t - c * 100;
            int ry = rem / 10; int e = rem - ry * 10;
            *(float4*)(sfeat + c * 400 + ry * 40 + e * 4) =
                *(const float4*)(fpb + (cb + c) * FPAD + (y0 + ry) * 40 + e * 4);
        }
        __syncthreads();

        int c1 = cslot * 2;
        float a[2][4] = {{0.f,0.f,0.f,0.f},{0.f,0.f,0.f,0.f}};
        const float* resb = s + yl * 32 + x0;
        for (int dyy = 0; dyy < 9; dyy++) {
            float4 rr[9];
            #pragma unroll
            for (int dx = 0; dx < 9; dx++)
                rr[dx] = *(const float4*)(resb + (dyy * 9 + dx) * 64);
            #pragma unroll
            for (int cc = 0; cc < 2; cc++) {
                const float* wp = sfeat + (c1 + cc) * 400 + (yl + dyy) * 40 + x0;
                float4 wa = *(const float4*)wp;
                float4 wb = *(const float4*)(wp + 4);
                float4 wc = *(const float4*)(wp + 8);
                float w[12] = {wa.x,wa.y,wa.z,wa.w, wb.x,wb.y,wb.z,wb.w, wc.x,wc.y,wc.z,wc.w};
                #pragma unroll
                for (int dx = 0; dx < 9; dx++) {
                    a[cc][0] += rr[dx].x * w[dx];
                    a[cc][1] += rr[dx].y * w[dx+1];
                    a[cc][2] += rr[dx].z * w[dx+2];
                    a[cc][3] += rr[dx].w * w[dx+3];
                }
            }
        }
        #pragma unroll
        for (int cc = 0; cc < 2; cc++) {
            int gi = (cb + c1 + cc) * NHW + (y0 + yl) * NW + x0;
            float4 fv = *(const float4*)(fltp + gi);
            float4 o;
            o.x = a[cc][0] + regw * fv.x;
            o.y = a[cc][1] + regw * fv.y;
            o.z = a[cc][2] + regw * fv.z;
            o.w = a[cc][3] + regw * fv.w;
            *(float4*)(fgb + gi) = o;
            an[0] += o.x*o.x; an[1] += o.y*o.y; an[2] += o.z*o.z; an[3] += o.w*o.w;
        }
    }

    __syncthreads();
    #pragma unroll
    for (int j = 0; j < 4; j++)
        sfeat[cslot * 64 + yl * 32 + x0 + j] = an[j];
    __syncthreads();
    if (tid < 64) {
        int yy = tid >> 5, x = tid & 31;
        float a = 0.f;
        #pragma unroll
        for (int cs = 0; cs < 8; cs++) a += sfeat[cs * 64 + yy * 32 + x];
        g_anum[hf * (NB*NHW) + bi * NHW + (y0 + yy) * NW + x] = a;
    }
}

// ---------------- K3: corr(fg) -> aden -> alpha -> fused update ----------------
__global__ __launch_bounds__(288) void k_corr_grad(const float* __restrict__ flt_in,
                                                   int use_in, float* __restrict__ out, int last) {
    __shared__ float s[8128];
    int tid = threadIdx.x;
    int h = tid / 72;
    int r = tid - h * 72;
    int dy = r >> 3;
    int x0 = (r & 7) * 4;
    int bi = blockIdx.x >> 5;
    int y0 = blockIdx.x & 31;

    const float* fgp = g_fg + bi * NCHW + y0 * NW;
    const float* fpb = g_featpad + bi * FPAD_C + y0 * 40;
    float* sflt  = s + h * 128;
    float* sfeat = s + 512 + h * 1440;

    float acc[4][9];
    #pragma unroll
    for (int j = 0; j < 4; j++)
        #pragma unroll
        for (int d = 0; d < 9; d++) acc[j][d] = 0.f;

    for (int ci = 0; ci < 16; ci++) {
        int cb = (h << 6) + (ci << 2);
        __syncthreads();
        if (r < 32) {
            int c = r >> 3, e = r & 7;
            *(float4*)(sflt + c * 32 + e * 4) = *(const float4*)(fgp + (cb + c) * NHW + e * 4);
        }
        #pragma unroll
        for (int i = 0; i < 5; i++) {
            int t = r + i * 72;
            int c = t / 90; int rem = t - c * 90;
            int ry = rem / 10; int e = rem - ry * 10;
            *(float4*)(sfeat + c * 360 + ry * 40 + e * 4) =
                *(const float4*)(fpb + (cb + c) * FPAD + ry * 40 + e * 4);
        }
        __syncthreads();
        #pragma unroll
        for (int c = 0; c < 4; c++) {
            float4 f = *(const float4*)(sflt + c * 32 + x0);
            const float* wp = sfeat + c * 360 + dy * 40 + x0;
            float4 wa = *(const float4*)wp;
            float4 wb = *(const float4*)(wp + 4);
            float4 wc = *(const float4*)(wp + 8);
            float w[12] = {wa.x,wa.y,wa.z,wa.w, wb.x,wb.y,wb.z,wb.w, wc.x,wc.y,wc.z,wc.w};
            #pragma unroll
            for (int dx = 0; dx < 9; dx++) {
                acc[0][dx] += f.x * w[dx];
                acc[1][dx] += f.y * w[dx+1];
                acc[2][dx] += f.z * w[dx+2];
                acc[3][dx] += f.w * w[dx+3];
            }
        }
    }

    __syncthreads();
    if (h > 0) {
        float* ap = s + (h - 1) * 2592 + r * 36;
        #pragma unroll
        for (int j = 0; j < 4; j++)
            #pragma unroll
            for (int dx = 0; dx < 9; dx++) ap[j * 9 + dx] = acc[j][dx];
    }
    __syncthreads();

    if (h == 0) {
        #pragma unroll
        for (int hh = 0; hh < 3; hh++) {
            const float* ap = s + hh * 2592 + r * 36;
            #pragma unroll
            for (int j = 0; j < 4; j++)
                #pragma unroll
                for (int dx = 0; dx < 9; dx++) acc[j][dx] += ap[j * 9 + dx];
        }
        float denl[4] = {0.f, 0.f, 0.f, 0.f};
        #pragma unroll
        for (int dx = 0; dx < 9; dx++) {
            int k = dy * 9 + dx;
            #pragma unroll
            for (int j = 0; j < 4; j++) {
                int gi = ((bi * NK + k) * NH + y0) * NW + x0 + j;
                float sg = g_maskw[gi] * acc[j][dx];
                denl[j] += sg * sg;
            }
        }
        #pragma unroll
        for (int j = 0; j < 4; j++)
            s[7776 + dy * 32 + x0 + j] = denl[j];
    }
    __syncthreads();

    if (tid < 32) {
        int x = tid;
        float d = 0.f;
        #pragma unroll
        for (int q = 0; q < 9; q++) d += s[7776 + q * 32 + x];
        int pi = bi * NHW + y0 * NW + x;
        float num = g_anum[pi] + g_anum[NB*NHW + pi];
        float ad = fmaxf(d + g_regw * num, 1e-8f);
        s[8064 + x] = num / ad;
    }
    __syncthreads();

    const float* fbase = use_in ? flt_in : g_flt;
    float* dst = last ? out : g_flt;
    float step = g_step;
    for (int t = tid; t < 2048; t += 288) {
        int c = t >> 3; int e = t & 7;
        int gi = bi * NCHW + c * NHW + y0 * NW + e * 4;
        float4 fg4 = *(const float4*)(g_fg + gi);
        float4 fv  = *(const float4*)(fbase + gi);
        float al0 = s[8064 + e * 4 + 0];
        float al1 = s[8064 + e * 4 + 1];
        float al2 = s[8064 + e * 4 + 2];
        float al3 = s[8064 + e * 4 + 3];
        float4 o;
        o.x = fv.x - step * al0 * fg4.x;
        o.y = fv.y - step * al1 * fg4.y;
        o.z = fv.z - step * al2 * fg4.z;
        o.w = fv.w - step * al3 * fg4.w;
        *(float4*)(dst + gi) = o;
    }
}

// ---------------- loss tail ----------------
__global__ void k_loss_out(float* __restrict__ out) {
    int t = threadIdx.x;
    if (t < 9) {
        float v;
        if (t < 3)       v = g_losses[t * 2] + g_losses[t * 2 + 1];
        else if (t < 6)  v = g_losses[(t - 3) * 2];
        else             v = g_losses[(t - 6) * 2 + 1];
        out[OUT_FLT + t] = v;
    }
}

extern "C" void kernel_launch(void* const* d_in, const int* in_sizes, int n_in,
                              void* d_out, int out_size) {
    const float* flt  = (const float*)d_in[0];
    const float* feat = (const float*)d_in[1];
    const float* lw   = (const float*)d_in[2];
    const float* mw   = (const float*)d_in[3];
    const float* sw   = (const float*)d_in[4];
    const float* ls   = (const float*)d_in[5];
    const float* fr   = (const float*)d_in[6];
    float* out = (float*)d_out;

    k_init<<<1, 128>>>(lw, mw, sw, ls, fr);
    k_prepad<<<4096, 128>>>(feat);
    for (int it = 0; it < 3; it++) {
        int first = (it == 0) ? 1 : 0;
        int last  = (it == 2) ? 1 : 0;
        k_corr_res<<<512, 288>>>(flt, first);
        k_transpose<<<512, 128>>>(flt, first, it);
        k_corr_grad<<<512, 288>>>(flt, first, out, last);
    }
    k_loss_out<<<1, 32>>>(out);
}